// round 6
// baseline (speedup 1.0000x reference)
#include <cuda_runtime.h>
#include <cuda_bf16.h>

// ProbsToSpan: B=16, S=4096.
// reference: mat = start ⊗ end^T; upper = triu(mat);
//   predicted_start = argmax_s max_t upper[s,t]
//   predicted_end   = argmax_t max_s upper[s,t]
// Inputs are uniform[0,1) (non-negative). fp32 multiply by a non-negative
// constant is monotone under round-to-nearest, so:
//   row_max[s] = start[s] * suffix_max(end)[s]   (bit-exact vs reference)
//   col_max[t] = end[t]   * prefix_max(start)[t]
// The [S,S] matrix never needs to exist. O(B*S): 512 KB read, 128 B written
// -> launch-latency bound. One launch, grid = B = 16 CTAs.

#define SLEN 4096
#define TPB  256
#define NW   (TPB / 32)           // 8 warps
#define CHUNK (SLEN / TPB)        // 16 contiguous elements per thread

__global__ __launch_bounds__(TPB, 1)
void ProbsToSpan_49143015801170_kernel(const float* __restrict__ start_p,
                                       const float* __restrict__ end_p,
                                       float* __restrict__ out, int B) {
    const int b    = blockIdx.x;
    const int tid  = threadIdx.x;
    const int lane = tid & 31;
    const int wid  = tid >> 5;          // 0..NW-1
    const int base = tid * CHUNK;       // 64B-aligned element offset

    const float* sp = start_p + (size_t)b * SLEN;
    const float* ep = end_p   + (size_t)b * SLEN;

    // Front-batched float4 loads: 8 independent LDG.128 per thread (MLP=8).
    float st[CHUNK], en[CHUNK];
    const float4* sp4 = (const float4*)(sp + base);
    const float4* ep4 = (const float4*)(ep + base);
#pragma unroll
    for (int i = 0; i < CHUNK / 4; i++) {
        float4 a = sp4[i];
        float4 c = ep4[i];
        st[4*i+0] = a.x; st[4*i+1] = a.y; st[4*i+2] = a.z; st[4*i+3] = a.w;
        en[4*i+0] = c.x; en[4*i+1] = c.y; en[4*i+2] = c.z; en[4*i+3] = c.w;
    }

    // Per-chunk maxima. Inputs in [0,1): 0.0f is a safe identity.
    float smax = 0.f, emax = 0.f;
#pragma unroll
    for (int i = 0; i < CHUNK; i++) {
        smax = fmaxf(smax, st[i]);
        emax = fmaxf(emax, en[i]);
    }

    // Warp inclusive PREFIX-max of smax (ascending lanes).
    float sincl = smax;
#pragma unroll
    for (int off = 1; off < 32; off <<= 1) {
        float o = __shfl_up_sync(0xffffffffu, sincl, off);
        if (lane >= off) sincl = fmaxf(sincl, o);
    }
    float sexcl = __shfl_up_sync(0xffffffffu, sincl, 1);
    if (lane == 0) sexcl = 0.f;

    // Warp inclusive SUFFIX-max of emax (descending lanes).
    float eincl = emax;
#pragma unroll
    for (int off = 1; off < 32; off <<= 1) {
        float o = __shfl_down_sync(0xffffffffu, eincl, off);
        if (lane < 32 - off) eincl = fmaxf(eincl, o);
    }
    float eexcl = __shfl_down_sync(0xffffffffu, eincl, 1);
    if (lane == 31) eexcl = 0.f;

    // Cross-warp combine (NW warps).
    __shared__ float wstot[NW], wetot[NW];
    if (lane == 31) wstot[wid] = sincl;   // warp's total start-max
    if (lane == 0)  wetot[wid] = eincl;   // warp's total end-max
    __syncthreads();

    float wprev = 0.f;
    for (int w = 0; w < wid; w++)      wprev = fmaxf(wprev, wstot[w]);
    float wnext = 0.f;
    for (int w = wid + 1; w < NW; w++) wnext = fmaxf(wnext, wetot[w]);

    const float excl_pref_start = fmaxf(sexcl, wprev); // max start[0..base-1]
    const float excl_suff_end   = fmaxf(eexcl, wnext); // max end[base+CHUNK..S-1]

    // predicted_end: col_max[t] = end[t] * prefix_max_start[t]; ascending scan,
    // strict '>' keeps first (smallest) index on ties -> jnp.argmax semantics.
    float runs = excl_pref_start;
    float bestAv = -1.f; int bestAi = 0;
#pragma unroll
    for (int i = 0; i < CHUNK; i++) {
        runs = fmaxf(runs, st[i]);
        float v = en[i] * runs;
        if (v > bestAv) { bestAv = v; bestAi = base + i; }
    }

    // predicted_start: row_max[s] = start[s] * suffix_max_end[s]; descending
    // scan, '>=' keeps the smallest index winning on ties.
    float rune = excl_suff_end;
    float bestBv = -1.f; int bestBi = 0;
#pragma unroll
    for (int i = CHUNK - 1; i >= 0; i--) {
        rune = fmaxf(rune, en[i]);
        float v = st[i] * rune;
        if (v >= bestBv) { bestBv = v; bestBi = base + i; }
    }

    // Warp argmax reduction: larger value wins; ties -> smaller index.
#pragma unroll
    for (int off = 16; off >= 1; off >>= 1) {
        float ov = __shfl_xor_sync(0xffffffffu, bestAv, off);
        int   oi = __shfl_xor_sync(0xffffffffu, bestAi, off);
        if (ov > bestAv || (ov == bestAv && oi < bestAi)) { bestAv = ov; bestAi = oi; }
        float pv = __shfl_xor_sync(0xffffffffu, bestBv, off);
        int   pi = __shfl_xor_sync(0xffffffffu, bestBi, off);
        if (pv > bestBv || (pv == bestBv && pi < bestBi)) { bestBv = pv; bestBi = pi; }
    }

    __shared__ float svA[NW], svB[NW];
    __shared__ int   siA[NW], siB[NW];
    if (lane == 0) {
        svA[wid] = bestAv; siA[wid] = bestAi;
        svB[wid] = bestBv; siB[wid] = bestBi;
    }
    __syncthreads();

    if (tid == 0) {
        float va = svA[0]; int ia = siA[0];
        float vb = svB[0]; int ib = siB[0];
#pragma unroll
        for (int w = 1; w < NW; w++) {
            if (svA[w] > va || (svA[w] == va && siA[w] < ia)) { va = svA[w]; ia = siA[w]; }
            if (svB[w] > vb || (svB[w] == vb && siB[w] < ib)) { vb = svB[w]; ib = siB[w]; }
        }
        out[b]     = (float)ib;  // predicted_start
        out[B + b] = (float)ia;  // predicted_end
    }
}

extern "C" void kernel_launch(void* const* d_in, const int* in_sizes, int n_in,
                              void* d_out, int out_size) {
    const float* start_p = (const float*)d_in[0];
    const float* end_p   = (const float*)d_in[1];
    float* out = (float*)d_out;
    int B = in_sizes[0] / SLEN;   // 16
    ProbsToSpan_49143015801170_kernel<<<B, TPB>>>(start_p, end_p, out, B);
}